// round 16
// baseline (speedup 1.0000x reference)
#include <cuda_runtime.h>
#include <cuda_bf16.h>
#include <cstdint>

#define B_TOT   32768
#define SAMP    16
#define D       256
#define NREL    238
#define BM      64
#define NTHREADS 256

// ---------------- device-global scratch ----------------
// W packed as tf32(RN-rounded) B-fragments for mma.m16n8k8.row.col:
// entry e = i*1024 + j*32 + lane  (i = k8-step 0..31, j = 8-col n-tile 0..31)
// holds {W[n][k], W[n][k+4]} with n = j*8 + (lane>>2), k = i*8 + (lane&3).
__device__ __align__(16) uint2 g_Bf[32768];       // 256 KB
__device__ __align__(16) float g_rwT[NREL * D];   // relation_weight transposed [r][d]

// ---------------- smem layout for k_main (bytes) ----------------
#define SM_IDX   0              // 1024 ints = 4096
#define SM_A     4096           // 64 rows * 1040 B (256 fp32 + 16B pad)
#define SM_TOTAL 70656
#define A_PITCH  1040           // 260 words; 260 % 32 = 4 -> conflict-free ldsm/STS

// ---------------- helpers ----------------
__device__ __forceinline__ uint32_t smem_u32(const void* p) {
    uint32_t a;
    asm("{ .reg .u64 t; cvta.to.shared.u64 t, %1; cvt.u32.u64 %0, t; }" : "=r"(a) : "l"(p));
    return a;
}
__device__ __forceinline__ uint32_t tf32_rn(float x) {
    uint32_t u;
    asm("cvt.rna.tf32.f32 %0, %1;" : "=r"(u) : "f"(x));
    return u;
}
__device__ __forceinline__ void ldsm4(uint32_t& r0, uint32_t& r1, uint32_t& r2,
                                      uint32_t& r3, uint32_t addr) {
    asm volatile("ldmatrix.sync.aligned.m8n8.x4.shared.b16 {%0,%1,%2,%3}, [%4];"
                 : "=r"(r0), "=r"(r1), "=r"(r2), "=r"(r3) : "r"(addr));
}
__device__ __forceinline__ void mma_tf32(float* c, const uint32_t* a, const uint32_t* b) {
    asm volatile("mma.sync.aligned.m16n8k8.row.col.f32.tf32.tf32.f32 "
                 "{%0,%1,%2,%3}, {%4,%5,%6,%7}, {%8,%9}, {%0,%1,%2,%3};"
                 : "+f"(c[0]), "+f"(c[1]), "+f"(c[2]), "+f"(c[3])
                 : "r"(a[0]), "r"(a[1]), "r"(a[2]), "r"(a[3]), "r"(b[0]), "r"(b[1]));
}

// ---------------- kernel 0: transpose rw + pack W tf32(RN) fragments ----------------
__global__ void k_prep0(const float* __restrict__ rw, const float* __restrict__ W) {
    const int tid = threadIdx.x;
    const int bx  = blockIdx.x;

    g_rwT[bx * D + tid] = rw[tid * NREL + bx];

    if (bx < 64) {
        #pragma unroll
        for (int r = 0; r < 2; ++r) {
            const int e = bx * 512 + r * 256 + tid;   // 0..32767
            const int l = e & 31;
            const int j = (e >> 5) & 31;
            const int i = e >> 10;
            const int n = j * 8 + (l >> 2);
            const int k = i * 8 + (l & 3);
            uint2 v;
            v.x = tf32_rn(W[n * 256 + k]);
            v.y = tf32_rn(W[n * 256 + k + 4]);
            g_Bf[e] = v;
        }
    }
}

// ---------------- kernel 1: rel->out, gather->smem(tf32), N-split GEMM, epilogue ------
__global__ __launch_bounds__(NTHREADS, 2) void k_main(const int* __restrict__ nbr,
                                                      const int* __restrict__ rel,
                                                      const float* __restrict__ feat,
                                                      float* __restrict__ out) {
    extern __shared__ char smem[];
    const uint32_t sbase = smem_u32(smem);
    const int tid  = threadIdx.x;
    const int b0   = blockIdx.x * BM;
    const int lane = tid & 31;
    const int warp = tid >> 5;

    ((int4*)(smem + SM_IDX))[tid] = ((const int4*)(nbr + b0 * SAMP))[tid];
    __syncthreads();

    // ---------- Phase R: relation means -> parked in out[] (proven R13 mechanism) ------
    {
        const float4* T4 = (const float4*)g_rwT;
        float4* O4 = (float4*)out;
        for (int i = 0; i < 8; ++i) {
            const int row = warp * 8 + i;
            const int* ids = rel + (b0 + row) * SAMP;
            float4 lo = make_float4(0.f, 0.f, 0.f, 0.f);
            float4 hi = make_float4(0.f, 0.f, 0.f, 0.f);
            #pragma unroll
            for (int s = 0; s < SAMP; ++s) {
                const int r = __ldg(ids + s);
                float4 vl = __ldg(&T4[r * 64 + lane]);
                float4 vh = __ldg(&T4[r * 64 + 32 + lane]);
                lo.x += vl.x; lo.y += vl.y; lo.z += vl.z; lo.w += vl.w;
                hi.x += vh.x; hi.y += vh.y; hi.z += vh.z; hi.w += vh.w;
            }
            const float inv = 1.f / 16.f;
            lo.x *= inv; lo.y *= inv; lo.z *= inv; lo.w *= inv;
            hi.x *= inv; hi.y *= inv; hi.z *= inv; hi.w *= inv;
            __stcg(&O4[(b0 + row) * 64 + lane], lo);
            __stcg(&O4[(b0 + row) * 64 + 32 + lane], hi);
        }
    }

    // ---------- Phase A: gather + mean (L2-only), tf32(RN) fp32 to smem ----------
    {
        const int q = tid & 63;
        const int g = tid >> 6;
        const float4* F4 = (const float4*)feat;
        const int* sIdx = (const int*)(smem + SM_IDX);
        #pragma unroll 2
        for (int k = 0; k < 16; ++k) {
            const int row = g * 16 + k;
            const int* ids = sIdx + row * SAMP;
            float4 a = make_float4(0.f, 0.f, 0.f, 0.f);
            #pragma unroll
            for (int s = 0; s < SAMP; ++s) {
                const int n = ids[s];
                float4 v = __ldcg(&F4[n * 64 + q]);
                a.x += v.x; a.y += v.y; a.z += v.z; a.w += v.w;
            }
            const float inv = 1.f / 16.f;
            uint4 w;
            w.x = tf32_rn(a.x * inv);
            w.y = tf32_rn(a.y * inv);
            w.z = tf32_rn(a.z * inv);
            w.w = tf32_rn(a.w * inv);
            *(uint4*)(smem + SM_A + row * A_PITCH + q * 16) = w;
        }
    }
    __syncthreads();        // also orders Phase R's out-writes for C-init reads below

    // ---------- Phase B: N-split GEMM, two 128-col halves, C-init = rel from out ------
    const uint32_t aAddr = sbase + SM_A + (uint32_t)(lane & 15) * A_PITCH + ((lane >> 4) << 4);
    const int rowl = lane >> 2;

    for (int h = 0; h < 2; ++h) {
        const int colb = h * 128 + warp * 16 + (lane & 3) * 2;
        float c[4][2][4];
        // C init from parked rel means
        #pragma unroll
        for (int mt = 0; mt < 4; ++mt) {
            const int r0 = b0 + rowl + mt * 16;
            const int r1 = r0 + 8;
            #pragma unroll
            for (int nt = 0; nt < 2; ++nt) {
                const int col = colb + nt * 8;
                float2 rv0 = __ldcg((const float2*)&out[r0 * D + col]);
                float2 rv1 = __ldcg((const float2*)&out[r1 * D + col]);
                c[mt][nt][0] = rv0.x; c[mt][nt][1] = rv0.y;
                c[mt][nt][2] = rv1.x; c[mt][nt][3] = rv1.y;
            }
        }

        const int jb = (h * 16 + warp * 2) * 32 + lane;
        uint2 bf[2][2];
        #pragma unroll
        for (int nt = 0; nt < 2; ++nt) bf[0][nt] = g_Bf[jb + nt * 32];

        #pragma unroll 4
        for (int i = 0; i < 32; ++i) {
            const int cur = i & 1, nxt = cur ^ 1;
            if (i < 31) {
                const int base = (i + 1) * 1024 + jb;
                #pragma unroll
                for (int nt = 0; nt < 2; ++nt) bf[nxt][nt] = g_Bf[base + nt * 32];
            }
            #pragma unroll
            for (int mt = 0; mt < 4; ++mt) {
                uint32_t aF[4];
                ldsm4(aF[0], aF[1], aF[2], aF[3],
                      aAddr + (uint32_t)(mt * 16) * A_PITCH + (uint32_t)(i * 32));
                #pragma unroll
                for (int nt = 0; nt < 2; ++nt)
                    mma_tf32(c[mt][nt], aF, (const uint32_t*)&bf[cur][nt]);
            }
        }

        // epilogue for this half: relu + streaming store
        #pragma unroll
        for (int mt = 0; mt < 4; ++mt) {
            const int r0 = b0 + rowl + mt * 16;
            const int r1 = r0 + 8;
            #pragma unroll
            for (int nt = 0; nt < 2; ++nt) {
                const int col = colb + nt * 8;
                float2 o0, o1;
                o0.x = fmaxf(c[mt][nt][0], 0.f);
                o0.y = fmaxf(c[mt][nt][1], 0.f);
                o1.x = fmaxf(c[mt][nt][2], 0.f);
                o1.y = fmaxf(c[mt][nt][3], 0.f);
                __stcs((float2*)&out[r0 * D + col], o0);
                __stcs((float2*)&out[r1 * D + col], o1);
            }
        }
    }
}

// ---------------- launch ----------------
extern "C" void kernel_launch(void* const* d_in, const int* in_sizes, int n_in,
                              void* d_out, int out_size) {
    (void)in_sizes; (void)n_in; (void)out_size;
    const int*   nbr  = (const int*)d_in[0];
    const int*   rel  = (const int*)d_in[1];
    const float* feat = (const float*)d_in[2];
    const float* W    = (const float*)d_in[3];
    const float* rw   = (const float*)d_in[4];
    float* out = (float*)d_out;

    cudaFuncSetAttribute(k_main, cudaFuncAttributeMaxDynamicSharedMemorySize, SM_TOTAL);

    k_prep0<<<NREL, 256>>>(rw, W);
    k_main<<<B_TOT / BM, NTHREADS, SM_TOTAL>>>(nbr, rel, feat, out);
}

// round 17
// speedup vs baseline: 1.0456x; 1.0456x over previous
#include <cuda_runtime.h>
#include <cuda_bf16.h>
#include <cstdint>

#define B_TOT   32768
#define SAMP    16
#define D       256
#define NREL    238
#define BM      64
#define NTHREADS 256

// ---------------- device-global scratch ----------------
// W packed as tf32(RN) B-fragments for mma.m16n8k8.row.col (proven R15/R16 map).
__device__ __align__(16) uint2 g_Bf[32768];       // 256 KB
__device__ __align__(16) float g_rwT[NREL * D];   // relation_weight transposed [r][d]

// ---------------- smem layout for k_main (bytes) ----------------
#define SM_IDX    0             // 1024 ints = 4096
#define SM_ABUF   4096          // 2 x (64 rows * 272 B) = 34816
#define AB_PITCH  272           // 68 words; 68 % 32 = 4 -> conflict-free ldsm/STS
#define AB_SIZE   17408
#define SM_REL    4096          // overlays A bufs after GEMM: 64 * 1040
#define REL_PITCH_B 1040
#define SM_TOTAL  70656

// ---------------- helpers ----------------
__device__ __forceinline__ uint32_t smem_u32(const void* p) {
    uint32_t a;
    asm("{ .reg .u64 t; cvta.to.shared.u64 t, %1; cvt.u32.u64 %0, t; }" : "=r"(a) : "l"(p));
    return a;
}
__device__ __forceinline__ uint32_t tf32_rn(float x) {
    uint32_t u;
    asm("cvt.rna.tf32.f32 %0, %1;" : "=r"(u) : "f"(x));
    return u;
}
__device__ __forceinline__ void ldsm4(uint32_t& r0, uint32_t& r1, uint32_t& r2,
                                      uint32_t& r3, uint32_t addr) {
    asm volatile("ldmatrix.sync.aligned.m8n8.x4.shared.b16 {%0,%1,%2,%3}, [%4];"
                 : "=r"(r0), "=r"(r1), "=r"(r2), "=r"(r3) : "r"(addr));
}
__device__ __forceinline__ void mma_tf32(float* c, const uint32_t* a, const uint32_t* b) {
    asm volatile("mma.sync.aligned.m16n8k8.row.col.f32.tf32.tf32.f32 "
                 "{%0,%1,%2,%3}, {%4,%5,%6,%7}, {%8,%9}, {%0,%1,%2,%3};"
                 : "+f"(c[0]), "+f"(c[1]), "+f"(c[2]), "+f"(c[3])
                 : "r"(a[0]), "r"(a[1]), "r"(a[2]), "r"(a[3]), "r"(b[0]), "r"(b[1]));
}

// ---------------- kernel 0: transpose rw + pack W tf32(RN) fragments (proven R16) ----
__global__ void k_prep0(const float* __restrict__ rw, const float* __restrict__ W) {
    const int tid = threadIdx.x;
    const int bx  = blockIdx.x;

    g_rwT[bx * D + tid] = rw[tid * NREL + bx];

    if (bx < 64) {
        #pragma unroll
        for (int r = 0; r < 2; ++r) {
            const int e = bx * 512 + r * 256 + tid;
            const int l = e & 31;
            const int j = (e >> 5) & 31;
            const int i = e >> 10;
            const int n = j * 8 + (l >> 2);
            const int k = i * 8 + (l & 3);
            uint2 v;
            v.x = tf32_rn(W[n * 256 + k]);
            v.y = tf32_rn(W[n * 256 + k + 4]);
            g_Bf[e] = v;
        }
    }
}

// ---------------- kernel 1: pipelined gather/GEMM -> rel -> epilogue ----------------
__global__ __launch_bounds__(NTHREADS, 2) void k_main(const int* __restrict__ nbr,
                                                      const int* __restrict__ rel,
                                                      const float* __restrict__ feat,
                                                      float* __restrict__ out) {
    extern __shared__ char smem[];
    const uint32_t sbase = smem_u32(smem);
    const int tid  = threadIdx.x;
    const int b0   = blockIdx.x * BM;
    const int lane = tid & 31;
    const int warp = tid >> 5;

    ((int4*)(smem + SM_IDX))[tid] = ((const int4*)(nbr + b0 * SAMP))[tid];
    __syncthreads();
    const int* sIdx = (const int*)(smem + SM_IDX);

    // gather one 64-col chunk into A buffer `buf` (cols c*64 .. c*64+63)
    const int qg = tid & 15;                    // float4 col within chunk
    const int gg = tid >> 4;                    // 0..15 row group (4 rows)
    const float4* F4 = (const float4*)feat;
    auto gather_chunk = [&](int c, int buf) {
        char* dst = smem + SM_ABUF + buf * AB_SIZE;
        #pragma unroll
        for (int j = 0; j < 4; ++j) {
            const int row = gg * 4 + j;
            const int* ids = sIdx + row * SAMP;
            float4 a = make_float4(0.f, 0.f, 0.f, 0.f);
            #pragma unroll
            for (int s = 0; s < SAMP; ++s) {
                const int n = ids[s];
                float4 v = __ldcg(&F4[n * 64 + c * 16 + qg]);
                a.x += v.x; a.y += v.y; a.z += v.z; a.w += v.w;
            }
            const float inv = 1.f / 16.f;
            uint4 w;
            w.x = tf32_rn(a.x * inv);
            w.y = tf32_rn(a.y * inv);
            w.z = tf32_rn(a.z * inv);
            w.w = tf32_rn(a.w * inv);
            *(uint4*)(dst + row * AB_PITCH + qg * 16) = w;
        }
    };

    float c[4][4][4];                           // [mt][nt][frag], full N=256 (proven R15)
    #pragma unroll
    for (int mt = 0; mt < 4; ++mt)
        #pragma unroll
        for (int nt = 0; nt < 4; ++nt)
            #pragma unroll
            for (int r = 0; r < 4; ++r) c[mt][nt][r] = 0.f;

    const int jb = warp * 128 + lane;           // B fragment lane base (j0 = warp*4)
    const uint32_t aFragOff = (uint32_t)(lane & 15) * AB_PITCH + ((lane >> 4) << 4);

    // prologue: fill buffer 0 with chunk 0
    gather_chunk(0, 0);
    __syncthreads();

    for (int kc = 0; kc < 4; ++kc) {
        // issue next chunk's gather first (loads go in flight; other warps mma meanwhile)
        if (kc < 3) gather_chunk(kc + 1, (kc + 1) & 1);

        // mma on chunk kc
        const uint32_t abuf = sbase + SM_ABUF + (uint32_t)(kc & 1) * AB_SIZE + aFragOff;
        uint2 bf[2][4];
        {
            const int base = (kc * 8) * 1024 + jb;
            #pragma unroll
            for (int nt = 0; nt < 4; ++nt) bf[0][nt] = g_Bf[base + nt * 32];
        }
        #pragma unroll
        for (int i = 0; i < 8; ++i) {
            const int cur = i & 1, nxt = cur ^ 1;
            if (i < 7) {
                const int base = (kc * 8 + i + 1) * 1024 + jb;
                #pragma unroll
                for (int nt = 0; nt < 4; ++nt) bf[nxt][nt] = g_Bf[base + nt * 32];
            }
            #pragma unroll
            for (int mt = 0; mt < 4; ++mt) {
                uint32_t aF[4];
                ldsm4(aF[0], aF[1], aF[2], aF[3],
                      abuf + (uint32_t)(mt * 16) * AB_PITCH + (uint32_t)(i * 32));
                #pragma unroll
                for (int nt = 0; nt < 4; ++nt)
                    mma_tf32(c[mt][nt], aF, (const uint32_t*)&bf[cur][nt]);
            }
        }
        __syncthreads();                        // next buffer staged; mma reads done
    }

    // ---------- Phase C: relation means into smem (proven R11/R15) ----------
    {
        const float4* T4 = (const float4*)g_rwT;
        for (int i = 0; i < 8; ++i) {
            const int row = warp * 8 + i;
            const int* ids = rel + (b0 + row) * SAMP;
            float4 lo = make_float4(0.f, 0.f, 0.f, 0.f);
            float4 hi = make_float4(0.f, 0.f, 0.f, 0.f);
            #pragma unroll
            for (int s = 0; s < SAMP; ++s) {
                const int r = __ldg(ids + s);
                float4 vl = __ldg(&T4[r * 64 + lane]);
                float4 vh = __ldg(&T4[r * 64 + 32 + lane]);
                lo.x += vl.x; lo.y += vl.y; lo.z += vl.z; lo.w += vl.w;
                hi.x += vh.x; hi.y += vh.y; hi.z += vh.z; hi.w += vh.w;
            }
            const float inv = 1.f / 16.f;
            lo.x *= inv; lo.y *= inv; lo.z *= inv; lo.w *= inv;
            hi.x *= inv; hi.y *= inv; hi.z *= inv; hi.w *= inv;
            *(float4*)(smem + SM_REL + row * REL_PITCH_B + lane * 16)       = lo;
            *(float4*)(smem + SM_REL + row * REL_PITCH_B + 512 + lane * 16) = hi;
        }
    }
    __syncthreads();

    // ---------- Epilogue: + relation mean (smem), relu, streaming store ----------
    {
        const int colb = warp * 32 + (lane & 3) * 2;
        const int rowl = lane >> 2;
        #pragma unroll
        for (int mt = 0; mt < 4; ++mt) {
            const int r0l = rowl + mt * 16;
            const int r1l = r0l + 8;
            #pragma unroll
            for (int nt = 0; nt < 4; ++nt) {
                const int col = colb + nt * 8;
                float2 rv0 = *(const float2*)(smem + SM_REL + r0l * REL_PITCH_B + col * 4);
                float2 rv1 = *(const float2*)(smem + SM_REL + r1l * REL_PITCH_B + col * 4);
                float2 o0, o1;
                o0.x = fmaxf(c[mt][nt][0] + rv0.x, 0.f);
                o0.y = fmaxf(c[mt][nt][1] + rv0.y, 0.f);
                o1.x = fmaxf(c[mt][nt][2] + rv1.x, 0.f);
                o1.y = fmaxf(c[mt][nt][3] + rv1.y, 0.f);
                __stcs((float2*)&out[(b0 + r0l) * D + col], o0);
                __stcs((float2*)&out[(b0 + r1l) * D + col], o1);
            }
        }
    }
}

// ---------------- launch ----------------
extern "C" void kernel_launch(void* const* d_in, const int* in_sizes, int n_in,
                              void* d_out, int out_size) {
    (void)in_sizes; (void)n_in; (void)out_size;
    const int*   nbr  = (const int*)d_in[0];
    const int*   rel  = (const int*)d_in[1];
    const float* feat = (const float*)d_in[2];
    const float* W    = (const float*)d_in[3];
    const float* rw   = (const float*)d_in[4];
    float* out = (float*)d_out;

    cudaFuncSetAttribute(k_main, cudaFuncAttributeMaxDynamicSharedMemorySize, SM_TOTAL);

    k_prep0<<<NREL, 256>>>(rw, W);
    k_main<<<B_TOT / BM, NTHREADS, SM_TOTAL>>>(nbr, rel, feat, out);
}